// round 15
// baseline (speedup 1.0000x reference)
#include <cuda_runtime.h>
#include <math.h>
#include <cstdint>

#define BB 8
#define LL 8192
#define DD 256
#define WW 64
#define NW 128
#define RW 512   /* B*W reduction rows per window */
#define LB 132   /* padded smem row stride (floats) */

// Scratch (allocation-free rule: static __device__ arrays)
__device__ float g_A[(size_t)NW * DD * DD];    // A_n = a*I - Skk_n   (32 MB)
__device__ float g_Svk[(size_t)NW * DD * DD];  // Svk_n               (32 MB)
__device__ float g_Ms[(size_t)NW * DD * DD];   // M snapshots         (32 MB)

// ---- packed fp32x2 helpers (FFMA2) ----------------------------------------
__device__ __forceinline__ uint64_t pk2(float x) {
    uint64_t r; asm("mov.b64 %0, {%1, %1};" : "=l"(r) : "f"(x)); return r;
}
__device__ __forceinline__ void fma2(uint64_t& d, uint64_t a, uint64_t b) {
    asm("fma.rn.f32x2 %0, %1, %2, %3;" : "=l"(d) : "l"(a), "l"(b), "l"(d));
}
__device__ __forceinline__ float2 up2(uint64_t p) {
    float2 r; asm("mov.b64 {%0, %1}, %2;" : "=f"(r.x), "=f"(r.y) : "l"(p)); return r;
}

// ---------------------------------------------------------------------------
// Kernel 1: per-window sums, FFMA2 + dense b-fragment (round 13 winner).
// ---------------------------------------------------------------------------
__global__ __launch_bounds__(256, 2) void k_sums(const float* __restrict__ keysp,
                                                 const float* __restrict__ values,
                                                 const float* __restrict__ gammas,
                                                 const float* __restrict__ alpha) {
    const int n    = blockIdx.z >> 1;
    const bool isA = (blockIdx.z & 1) == 0;
    const int jBase = blockIdx.x * 128;
    const int iBase = blockIdx.y * 128;
    const float* __restrict__ left = isA ? keysp : values;

    __shared__ float Ls[2][16 * LB];
    __shared__ float Rs[2][16 * LB];

    const int tx = threadIdx.x, ty = threadIdx.y;
    const int tid = ty * 16 + tx;
    const int row0 = tid >> 5;
    const int row1 = row0 + 8;
    const int c4   = (tid & 31) * 4;

    uint64_t acc2[8][4];
#pragma unroll
    for (int a = 0; a < 8; a++)
#pragma unroll
        for (int b = 0; b < 4; b++) acc2[a][b] = 0ull;

    float4 lA0, lA1, rA0, rA1;
    float g0v, g1v;

#define LOADC(R0) do {                                                          \
        const int gr0 = (R0) + row0, gr1 = (R0) + row1;                         \
        const size_t o0 = ((size_t)(gr0 >> 6) * LL + n * WW + (gr0 & 63)) * DD; \
        const size_t o1 = ((size_t)(gr1 >> 6) * LL + n * WW + (gr1 & 63)) * DD; \
        g0v = gammas[(gr0 >> 6) * LL + n * WW + (gr0 & 63)];                    \
        g1v = gammas[(gr1 >> 6) * LL + n * WW + (gr1 & 63)];                    \
        lA0 = *(const float4*)(left  + o0 + iBase + c4);                        \
        lA1 = *(const float4*)(left  + o1 + iBase + c4);                        \
        rA0 = *(const float4*)(keysp + o0 + jBase + c4);                        \
        rA1 = *(const float4*)(keysp + o1 + jBase + c4);                        \
    } while (0)

#define STOREC(BUF) do {                                                        \
        float4 t;                                                               \
        t = lA0; t.x *= g0v; t.y *= g0v; t.z *= g0v; t.w *= g0v;                \
        *(float4*)&Ls[BUF][row0 * LB + c4] = t;                                 \
        t = lA1; t.x *= g1v; t.y *= g1v; t.z *= g1v; t.w *= g1v;                \
        *(float4*)&Ls[BUF][row1 * LB + c4] = t;                                 \
        *(float4*)&Rs[BUF][row0 * LB + c4] = rA0;                               \
        *(float4*)&Rs[BUF][row1 * LB + c4] = rA1;                               \
    } while (0)

    LOADC(0);
    STOREC(0);
    LOADC(16);
    __syncthreads();

    for (int c = 0; c < 32; c++) {
        const int cur = c & 1;
        if (c < 31) STOREC(cur ^ 1);
        if (c < 30) LOADC((c + 2) * 16);

#pragma unroll
        for (int kk = 0; kk < 16; kk++) {
            float4 la0 = *(const float4*)&Ls[cur][kk * LB + ty * 8];
            float4 la1 = *(const float4*)&Ls[cur][kk * LB + ty * 8 + 4];
            ulonglong2 lbp0 = *(const ulonglong2*)&Rs[cur][kk * LB + tx * 4];
            ulonglong2 lbp1 = *(const ulonglong2*)&Rs[cur][kk * LB + 64 + tx * 4];
            float laf[8] = {la0.x, la0.y, la0.z, la0.w, la1.x, la1.y, la1.z, la1.w};
#pragma unroll
            for (int a = 0; a < 8; a++) {
                const uint64_t ap = pk2(laf[a]);
                fma2(acc2[a][0], ap, lbp0.x);
                fma2(acc2[a][1], ap, lbp0.y);
                fma2(acc2[a][2], ap, lbp1.x);
                fma2(acc2[a][3], ap, lbp1.y);
            }
        }
        __syncthreads();
    }
#undef LOADC
#undef STOREC

    const float aSig = 1.f / (1.f + expf(-alpha[0]));
    float* dst = isA ? g_A : g_Svk;
    const size_t base = (size_t)n * DD * DD;
#pragma unroll
    for (int a = 0; a < 8; a++) {
        const int i = iBase + ty * 8 + a;
        float f[8];
        float2 p;
        p = up2(acc2[a][0]); f[0] = p.x; f[1] = p.y;
        p = up2(acc2[a][1]); f[2] = p.x; f[3] = p.y;
        p = up2(acc2[a][2]); f[4] = p.x; f[5] = p.y;
        p = up2(acc2[a][3]); f[6] = p.x; f[7] = p.y;
        if (isA) {
#pragma unroll
            for (int b = 0; b < 4; b++) {
                const int j0 = jBase + tx * 4 + b;
                const int j1 = jBase + 64 + tx * 4 + b;
                f[b]     = ((i == j0) ? aSig : 0.f) - f[b];
                f[b + 4] = ((i == j1) ? aSig : 0.f) - f[b + 4];
            }
        }
        *(float4*)(dst + base + (size_t)i * DD + jBase + tx * 4)      = *(float4*)&f[0];
        *(float4*)(dst + base + (size_t)i * DD + jBase + 64 + tx * 4) = *(float4*)&f[4];
    }
}

// ---------------------------------------------------------------------------
// Kernel 2: sequential scan, 4-CTA cluster (8 rows x 64-col quarters).
//   M_n[r, j] = sum_d M_{n-1}[r, d] * A_n[d, j] + Svk_n[r, j]
// grid 128 CTAs = 32 clusters of 4, block 512.
// Cluster c owns rows [8c, 8c+8); rank = column quarter (64 cols).
// Msm[buf][d][row] holds the full 8 rows x 256 cols state (double-buffered).
// Compute thread: jg = t&15 (4 cols), hq = (t>>4)&15 (16 d's), rh = t>>8
// (4 rows). FFMA2 inner loop; A float4 = 2 pre-packed f32x2 pairs.
// Combine thread: one (row, col) cell; store local + 3 partner DSMEM stores
// + 3 remote mbarrier arrives (count 1536), double-buffered parity.
// A chip traffic: 32 clusters x 256KB = 8 MB/window (half of round 12).
// ---------------------------------------------------------------------------
__global__ __launch_bounds__(512) __cluster_dims__(4, 1, 1) void k_scan() {
    __shared__ float Msm[2][DD][8];        // [buf][col d][row]  16 KB
    __shared__ float part[16][8][64];      // [hq][row][col-in-quarter] 32 KB
    __shared__ uint64_t mbar[2];

    const int t = threadIdx.x;

    uint32_t rank;
    asm("mov.u32 %0, %%cluster_ctarank;" : "=r"(rank));
    const int qBase = (int)rank * 64;
    const int r0 = (blockIdx.x >> 2) * 8;

    // compute mapping
    const int jg = t & 15;
    const int hq = (t >> 4) & 15;
    const int rh = t >> 8;                 // 0..1
    const int rBase = rh * 4;
    const int dBase = hq * 16;
    const int j4 = qBase + jg * 4;

    // combine mapping: one cell (cr, cj) per thread
    const int cr = t >> 6;                 // 0..7
    const int cj = t & 63;                 // 0..63
    const int cjg = qBase + cj;

    // zero buffer 0
    for (int i = t; i < DD * 8; i += 512) ((float*)Msm[0])[i] = 0.f;
    if (t < 2) {
        uint64_t tmp;
        asm("cvta.to.shared.u64 %0, %1;" : "=l"(tmp) : "l"((const void*)&mbar[t]));
        asm volatile("mbarrier.init.shared.b64 [%0], %1;"
                     :: "r"((uint32_t)tmp), "r"(1536u) : "memory");
    }
    __syncthreads();
    asm volatile("barrier.cluster.arrive.aligned;" ::: "memory");
    asm volatile("barrier.cluster.wait.aligned;" ::: "memory");

    uint32_t msmBase, mbarBase;
    {
        uint64_t tmp;
        asm("cvta.to.shared.u64 %0, %1;" : "=l"(tmp) : "l"((const void*)&Msm[0][0][0]));
        msmBase = (uint32_t)tmp;
        asm("cvta.to.shared.u64 %0, %1;" : "=l"(tmp) : "l"((const void*)&mbar[0]));
        mbarBase = (uint32_t)tmp;
    }
    // remote cell address (same offset each window except buffer term)
    const uint32_t cellOff = (uint32_t)((cjg * 8 + cr) * 4);

    // A tile for this thread: 16 d-rows x 4 cols, as pre-packed f32x2 pairs
    ulonglong2 av[16];
#pragma unroll
    for (int k = 0; k < 16; k++)
        av[k] = *(const ulonglong2*)(g_A + (size_t)(dBase + k) * DD + j4);

    for (int n = 0; n < NW; n++) {
        const int cur = n & 1;
        const int nb  = cur ^ 1;
        const uint32_t par = (uint32_t)((n >> 1) & 1);

        // hoisted Svk load for the combine phase
        const float sval = g_Svk[(size_t)n * DD * DD + (size_t)(r0 + cr) * DD + cjg];

        uint64_t acc[4][2];
#pragma unroll
        for (int r = 0; r < 4; r++) { acc[r][0] = 0ull; acc[r][1] = 0ull; }

#pragma unroll
        for (int k = 0; k < 16; k++) {
            const float4 m4 = *(const float4*)&Msm[cur][dBase + k][rBase];
            const uint64_t b0 = av[k].x, b1 = av[k].y;
            uint64_t ap;
            ap = pk2(m4.x); fma2(acc[0][0], ap, b0); fma2(acc[0][1], ap, b1);
            ap = pk2(m4.y); fma2(acc[1][0], ap, b0); fma2(acc[1][1], ap, b1);
            ap = pk2(m4.z); fma2(acc[2][0], ap, b0); fma2(acc[2][1], ap, b1);
            ap = pk2(m4.w); fma2(acc[3][0], ap, b0); fma2(acc[3][1], ap, b1);
        }

        // store partials (16B aligned: jg*4 floats)
#pragma unroll
        for (int r = 0; r < 4; r++)
            *(ulonglong2*)&part[hq][rBase + r][jg * 4] =
                make_ulonglong2(acc[r][0], acc[r][1]);

        // prefetch next window's A (independent of all sync below)
        if (n < NW - 1) {
            const float* __restrict__ An = g_A + (size_t)(n + 1) * DD * DD;
#pragma unroll
            for (int k = 0; k < 16; k++)
                av[k] = *(const ulonglong2*)(An + (size_t)(dBase + k) * DD + j4);
        }
        __syncthreads();

        // combine: one cell per thread
        float u = sval;
#pragma unroll
        for (int q = 0; q < 16; q++) u += part[q][cr][cj];

        const uint32_t laddr = msmBase + (uint32_t)(nb * DD * 8 * 4) + cellOff;
        asm volatile("st.shared.f32 [%0], %1;" :: "r"(laddr), "f"(u));
#pragma unroll
        for (int p = 1; p < 4; p++) {
            const uint32_t prank = (rank + (uint32_t)p) & 3u;
            uint32_t raddr;
            asm("mapa.shared::cluster.u32 %0, %1, %2;" : "=r"(raddr) : "r"(laddr), "r"(prank));
            asm volatile("st.shared::cluster.f32 [%0], %1;" :: "r"(raddr), "f"(u));
            uint32_t rmbar;
            asm("mapa.shared::cluster.u32 %0, %1, %2;"
                : "=r"(rmbar) : "r"(mbarBase + (uint32_t)(nb * 8)), "r"(prank));
            asm volatile("mbarrier.arrive.release.cluster.shared::cluster.b64 _, [%0];"
                         :: "r"(rmbar) : "memory");
        }

        // snapshot (coalesced: cj consecutive)
        g_Ms[(size_t)n * DD * DD + (size_t)(r0 + cr) * DD + cjg] = u;

        __syncthreads();   // local Msm[nb] stores visible CTA-wide

        // wait for 1536 partner arrivals (acquire orders their DSMEM stores)
        asm volatile(
            "{\n\t"
            ".reg .pred P;\n\t"
            "KSW_%=:\n\t"
            "mbarrier.try_wait.parity.acquire.cluster.shared::cta.b64 P, [%0], %1, 0x989680;\n\t"
            "@!P bra KSW_%=;\n\t"
            "}"
            :: "r"(mbarBase + (uint32_t)(nb * 8)), "r"(par) : "memory");
    }

    asm volatile("barrier.cluster.arrive.aligned;" ::: "memory");
    asm volatile("barrier.cluster.wait.aligned;" ::: "memory");
}

// ---------------------------------------------------------------------------
// Kernel 3: retrieval, FFMA2 + dense b-fragment (round 13 winner).
// ---------------------------------------------------------------------------
__global__ __launch_bounds__(256, 2) void k_out(const float* __restrict__ queries,
                                                float* __restrict__ out) {
    const int n = blockIdx.z;
    const int oBase = blockIdx.x * 128;
    const int uBase = blockIdx.y * 128;

    __shared__ float Qs[2][16 * LB];
    __shared__ float Mss[2][16 * LB];

    const int tx = threadIdx.x, ty = threadIdx.y;
    const int tid = ty * 16 + tx;
    const int ul0 = tid >> 2;
    const int ul1 = ul0 + 64;
    const int dq  = (tid & 3) * 4;

    const float* __restrict__ Mbase = g_Ms + (size_t)n * DD * DD;

    const int ug0 = uBase + ul0, ug1 = uBase + ul1;
    const size_t qoff0 = ((size_t)(ug0 >> 6) * LL + n * WW + (ug0 & 63)) * DD;
    const size_t qoff1 = ((size_t)(ug1 >> 6) * LL + n * WW + (ug1 & 63)) * DD;

    uint64_t acc2[8][4];
#pragma unroll
    for (int a = 0; a < 8; a++)
#pragma unroll
        for (int b = 0; b < 4; b++) acc2[a][b] = 0ull;

    float4 q0, q1, m0, m1;
#define LOADD(D0) do {                                                         \
        q0 = *(const float4*)(queries + qoff0 + (D0) + dq);                    \
        q1 = *(const float4*)(queries + qoff1 + (D0) + dq);                    \
        m0 = *(const float4*)(Mbase + (size_t)(oBase + ul0) * DD + (D0) + dq); \
        m1 = *(const float4*)(Mbase + (size_t)(oBase + ul1) * DD + (D0) + dq); \
    } while (0)

#define STORED(BUF) do {                                                       \
        Qs[BUF][(dq + 0) * LB + ul0] = q0.x; Qs[BUF][(dq + 1) * LB + ul0] = q0.y; \
        Qs[BUF][(dq + 2) * LB + ul0] = q0.z; Qs[BUF][(dq + 3) * LB + ul0] = q0.w; \
        Qs[BUF][(dq + 0) * LB + ul1] = q1.x; Qs[BUF][(dq + 1) * LB + ul1] = q1.y; \
        Qs[BUF][(dq + 2) * LB + ul1] = q1.z; Qs[BUF][(dq + 3) * LB + ul1] = q1.w; \
        Mss[BUF][(dq + 0) * LB + ul0] = m0.x; Mss[BUF][(dq + 1) * LB + ul0] = m0.y; \
        Mss[BUF][(dq + 2) * LB + ul0] = m0.z; Mss[BUF][(dq + 3) * LB + ul0] = m0.w; \
        Mss[BUF][(dq + 0) * LB + ul1] = m1.x; Mss[BUF][(dq + 1) * LB + ul1] = m1.y; \
        Mss[BUF][(dq + 2) * LB + ul1] = m1.z; Mss[BUF][(dq + 3) * LB + ul1] = m1.w; \
    } while (0)

    LOADD(0);
    STORED(0);
    LOADD(16);
    __syncthreads();

    for (int c = 0; c < 16; c++) {
        const int cur = c & 1;
        if (c < 15) STORED(cur ^ 1);
        if (c < 14) LOADD((c + 2) * 16);

#pragma unroll
        for (int kk = 0; kk < 16; kk++) {
            float4 la0 = *(const float4*)&Qs[cur][kk * LB + ty * 8];
            float4 la1 = *(const float4*)&Qs[cur][kk * LB + ty * 8 + 4];
            ulonglong2 lbp0 = *(const ulonglong2*)&Mss[cur][kk * LB + tx * 4];
            ulonglong2 lbp1 = *(const ulonglong2*)&Mss[cur][kk * LB + 64 + tx * 4];
            float laf[8] = {la0.x, la0.y, la0.z, la0.w, la1.x, la1.y, la1.z, la1.w};
#pragma unroll
            for (int a = 0; a < 8; a++) {
                const uint64_t ap = pk2(laf[a]);
                fma2(acc2[a][0], ap, lbp0.x);
                fma2(acc2[a][1], ap, lbp0.y);
                fma2(acc2[a][2], ap, lbp1.x);
                fma2(acc2[a][3], ap, lbp1.y);
            }
        }
        __syncthreads();
    }
#undef LOADD
#undef STORED

#pragma unroll
    for (int a = 0; a < 8; a++) {
        const int u = uBase + ty * 8 + a;
        const size_t orow = ((size_t)(u >> 6) * LL + n * WW + (u & 63)) * DD;
        float f[8];
        float2 p;
        p = up2(acc2[a][0]); f[0] = p.x; f[1] = p.y;
        p = up2(acc2[a][1]); f[2] = p.x; f[3] = p.y;
        p = up2(acc2[a][2]); f[4] = p.x; f[5] = p.y;
        p = up2(acc2[a][3]); f[6] = p.x; f[7] = p.y;
        *(float4*)(out + orow + oBase + tx * 4)      = *(float4*)&f[0];
        *(float4*)(out + orow + oBase + 64 + tx * 4) = *(float4*)&f[4];
    }
}

// ---------------------------------------------------------------------------
extern "C" void kernel_launch(void* const* d_in, const int* in_sizes, int n_in,
                              void* d_out, int out_size) {
    const float* keys    = (const float*)d_in[0];
    const float* values  = (const float*)d_in[1];
    const float* queries = (const float*)d_in[2];
    const float* gammas  = (const float*)d_in[3];
    const float* alpha   = (const float*)d_in[4];
    float* out = (float*)d_out;

    (void)in_sizes; (void)n_in; (void)out_size;

    dim3 blk(16, 16);
    k_sums<<<dim3(2, 2, NW * 2), blk>>>(keys, values, gammas, alpha);
    k_scan<<<128, 512>>>();
    k_out<<<dim3(2, 4, NW), blk>>>(queries, out);
}

// round 16
// speedup vs baseline: 1.2308x; 1.2308x over previous
#include <cuda_runtime.h>
#include <math.h>
#include <cstdint>

#define BB 8
#define LL 8192
#define DD 256
#define WW 64
#define NW 128
#define RW 512   /* B*W reduction rows per window */
#define LB 132   /* padded smem row stride (floats) */

// Scratch (allocation-free rule: static __device__ arrays)
__device__ float g_A[(size_t)NW * DD * DD];    // A_n = a*I - Skk_n   (32 MB)
__device__ float g_Svk[(size_t)NW * DD * DD];  // Svk_n               (32 MB)
__device__ float g_Ms[(size_t)NW * DD * DD];   // M snapshots         (32 MB)

// ---- packed fp32x2 helpers (FFMA2) ----------------------------------------
__device__ __forceinline__ uint64_t pk2(float x) {
    uint64_t r; asm("mov.b64 %0, {%1, %1};" : "=l"(r) : "f"(x)); return r;
}
__device__ __forceinline__ void fma2(uint64_t& d, uint64_t a, uint64_t b) {
    asm("fma.rn.f32x2 %0, %1, %2, %3;" : "=l"(d) : "l"(a), "l"(b), "l"(d));
}
__device__ __forceinline__ float2 up2(uint64_t p) {
    float2 r; asm("mov.b64 {%0, %1}, %2;" : "=f"(r.x), "=f"(r.y) : "l"(p)); return r;
}

// ---------------------------------------------------------------------------
// Kernel 1: per-window sums, FFMA2 + dense b-fragment (round 13 winner).
// ---------------------------------------------------------------------------
__global__ __launch_bounds__(256, 2) void k_sums(const float* __restrict__ keysp,
                                                 const float* __restrict__ values,
                                                 const float* __restrict__ gammas,
                                                 const float* __restrict__ alpha) {
    const int n    = blockIdx.z >> 1;
    const bool isA = (blockIdx.z & 1) == 0;
    const int jBase = blockIdx.x * 128;
    const int iBase = blockIdx.y * 128;
    const float* __restrict__ left = isA ? keysp : values;

    __shared__ float Ls[2][16 * LB];
    __shared__ float Rs[2][16 * LB];

    const int tx = threadIdx.x, ty = threadIdx.y;
    const int tid = ty * 16 + tx;
    const int row0 = tid >> 5;
    const int row1 = row0 + 8;
    const int c4   = (tid & 31) * 4;

    uint64_t acc2[8][4];
#pragma unroll
    for (int a = 0; a < 8; a++)
#pragma unroll
        for (int b = 0; b < 4; b++) acc2[a][b] = 0ull;

    float4 lA0, lA1, rA0, rA1;
    float g0v, g1v;

#define LOADC(R0) do {                                                          \
        const int gr0 = (R0) + row0, gr1 = (R0) + row1;                         \
        const size_t o0 = ((size_t)(gr0 >> 6) * LL + n * WW + (gr0 & 63)) * DD; \
        const size_t o1 = ((size_t)(gr1 >> 6) * LL + n * WW + (gr1 & 63)) * DD; \
        g0v = gammas[(gr0 >> 6) * LL + n * WW + (gr0 & 63)];                    \
        g1v = gammas[(gr1 >> 6) * LL + n * WW + (gr1 & 63)];                    \
        lA0 = *(const float4*)(left  + o0 + iBase + c4);                        \
        lA1 = *(const float4*)(left  + o1 + iBase + c4);                        \
        rA0 = *(const float4*)(keysp + o0 + jBase + c4);                        \
        rA1 = *(const float4*)(keysp + o1 + jBase + c4);                        \
    } while (0)

#define STOREC(BUF) do {                                                        \
        float4 t;                                                               \
        t = lA0; t.x *= g0v; t.y *= g0v; t.z *= g0v; t.w *= g0v;                \
        *(float4*)&Ls[BUF][row0 * LB + c4] = t;                                 \
        t = lA1; t.x *= g1v; t.y *= g1v; t.z *= g1v; t.w *= g1v;                \
        *(float4*)&Ls[BUF][row1 * LB + c4] = t;                                 \
        *(float4*)&Rs[BUF][row0 * LB + c4] = rA0;                               \
        *(float4*)&Rs[BUF][row1 * LB + c4] = rA1;                               \
    } while (0)

    LOADC(0);
    STOREC(0);
    LOADC(16);
    __syncthreads();

    for (int c = 0; c < 32; c++) {
        const int cur = c & 1;
        if (c < 31) STOREC(cur ^ 1);
        if (c < 30) LOADC((c + 2) * 16);

#pragma unroll
        for (int kk = 0; kk < 16; kk++) {
            float4 la0 = *(const float4*)&Ls[cur][kk * LB + ty * 8];
            float4 la1 = *(const float4*)&Ls[cur][kk * LB + ty * 8 + 4];
            ulonglong2 lbp0 = *(const ulonglong2*)&Rs[cur][kk * LB + tx * 4];
            ulonglong2 lbp1 = *(const ulonglong2*)&Rs[cur][kk * LB + 64 + tx * 4];
            float laf[8] = {la0.x, la0.y, la0.z, la0.w, la1.x, la1.y, la1.z, la1.w};
#pragma unroll
            for (int a = 0; a < 8; a++) {
                const uint64_t ap = pk2(laf[a]);
                fma2(acc2[a][0], ap, lbp0.x);
                fma2(acc2[a][1], ap, lbp0.y);
                fma2(acc2[a][2], ap, lbp1.x);
                fma2(acc2[a][3], ap, lbp1.y);
            }
        }
        __syncthreads();
    }
#undef LOADC
#undef STOREC

    const float aSig = 1.f / (1.f + expf(-alpha[0]));
    float* dst = isA ? g_A : g_Svk;
    const size_t base = (size_t)n * DD * DD;
#pragma unroll
    for (int a = 0; a < 8; a++) {
        const int i = iBase + ty * 8 + a;
        float f[8];
        float2 p;
        p = up2(acc2[a][0]); f[0] = p.x; f[1] = p.y;
        p = up2(acc2[a][1]); f[2] = p.x; f[3] = p.y;
        p = up2(acc2[a][2]); f[4] = p.x; f[5] = p.y;
        p = up2(acc2[a][3]); f[6] = p.x; f[7] = p.y;
        if (isA) {
#pragma unroll
            for (int b = 0; b < 4; b++) {
                const int j0 = jBase + tx * 4 + b;
                const int j1 = jBase + 64 + tx * 4 + b;
                f[b]     = ((i == j0) ? aSig : 0.f) - f[b];
                f[b + 4] = ((i == j1) ? aSig : 0.f) - f[b + 4];
            }
        }
        *(float4*)(dst + base + (size_t)i * DD + jBase + tx * 4)      = *(float4*)&f[0];
        *(float4*)(dst + base + (size_t)i * DD + jBase + 64 + tx * 4) = *(float4*)&f[4];
    }
}

// ---------------------------------------------------------------------------
// Kernel 2: sequential scan, 2-CTA cluster column split + mbarrier exchange
// (round-8 structure that delivered 809us total), FFMA2 compute phase.
//   M_n[r, j] = sum_d M_{n-1}[r, d] * A_n[d, j] + Svk_n[r, j]
// grid 128 CTAs (64 clusters of 2), block 512.
// Thread: jg = t&31 (4 cols), hq = t>>5 (16 d's). A float4 = 2 packed
// f32x2 pairs (zero packing); M rows broadcast via pk2.
// ---------------------------------------------------------------------------
__global__ __launch_bounds__(512) __cluster_dims__(2, 1, 1) void k_scan() {
    __shared__ float4 Msm4[2][DD];          // [buf][global col] rows r0..r0+3
    __shared__ float part[16][4][128];
    __shared__ uint64_t mbar[2];

    const int t = threadIdx.x;
    const int jg = t & 31;
    const int hq = t >> 5;                  // 0..15
    const int dBase = hq * 16;

    uint32_t rank;
    asm("mov.u32 %0, %%cluster_ctarank;" : "=r"(rank));
    const uint32_t prank = rank ^ 1u;
    const int ch = (int)rank;
    const int r0 = (blockIdx.x >> 1) * 4;
    const int j4 = ch * 128 + jg * 4;

    const int rr  = t >> 7;                 // 0..3
    const int jl  = t & 127;                // 0..127
    const int jgl = ch * 128 + jl;

    if (t < DD) Msm4[0][t] = make_float4(0.f, 0.f, 0.f, 0.f);
    if (t < 2) {
        uint32_t mb;
        {
            uint64_t tmp;
            asm("cvta.to.shared.u64 %0, %1;" : "=l"(tmp) : "l"((const void*)&mbar[t]));
            mb = (uint32_t)tmp;
        }
        asm volatile("mbarrier.init.shared.b64 [%0], %1;" :: "r"(mb), "r"(512u) : "memory");
    }
    __syncthreads();
    asm volatile("barrier.cluster.arrive.aligned;" ::: "memory");
    asm volatile("barrier.cluster.wait.aligned;" ::: "memory");

    uint32_t msmBase, mbarBase;
    {
        uint64_t tmp;
        asm("cvta.to.shared.u64 %0, %1;" : "=l"(tmp) : "l"((const void*)&Msm4[0][0]));
        msmBase = (uint32_t)tmp;
        asm("cvta.to.shared.u64 %0, %1;" : "=l"(tmp) : "l"((const void*)&mbar[0]));
        mbarBase = (uint32_t)tmp;
    }

    // A tile for this thread: 16 d-rows x 4 cols, as packed f32x2 pairs
    ulonglong2 av[16];
#pragma unroll
    for (int k = 0; k < 16; k++)
        av[k] = *(const ulonglong2*)(g_A + (size_t)(dBase + k) * DD + j4);

    for (int n = 0; n < NW; n++) {
        const int cur = n & 1;
        const int nb  = cur ^ 1;
        const uint32_t par = (uint32_t)((n >> 1) & 1);

        // hoisted Svk load (latency hidden under FMA stage)
        const float sval = g_Svk[(size_t)n * DD * DD + (size_t)(r0 + rr) * DD + jgl];

        uint64_t acc[4][2];
#pragma unroll
        for (int r = 0; r < 4; r++) { acc[r][0] = 0ull; acc[r][1] = 0ull; }

#pragma unroll
        for (int k = 0; k < 16; k++) {
            const float4 m4 = Msm4[cur][dBase + k];   // broadcast LDS.128
            const uint64_t b0 = av[k].x, b1 = av[k].y;
            uint64_t ap;
            ap = pk2(m4.x); fma2(acc[0][0], ap, b0); fma2(acc[0][1], ap, b1);
            ap = pk2(m4.y); fma2(acc[1][0], ap, b0); fma2(acc[1][1], ap, b1);
            ap = pk2(m4.z); fma2(acc[2][0], ap, b0); fma2(acc[2][1], ap, b1);
            ap = pk2(m4.w); fma2(acc[3][0], ap, b0); fma2(acc[3][1], ap, b1);
        }

        // store partials (16B aligned)
#pragma unroll
        for (int r = 0; r < 4; r++)
            *(ulonglong2*)&part[hq][r][jg * 4] = make_ulonglong2(acc[r][0], acc[r][1]);

        // prefetch next window's A (independent of all sync below)
        if (n < NW - 1) {
            const float* __restrict__ An = g_A + (size_t)(n + 1) * DD * DD;
#pragma unroll
            for (int k = 0; k < 16; k++)
                av[k] = *(const ulonglong2*)(An + (size_t)(dBase + k) * DD + j4);
        }
        __syncthreads();

        float u = 0.f;
#pragma unroll
        for (int q = 0; q < 16; q++) u += part[q][rr][jl];
        u += sval;

        // write own half into local next buffer + partner's next buffer
        const uint32_t off = (uint32_t)(nb * DD * 16 + (jgl * 4 + rr) * 4);
        const uint32_t laddr = msmBase + off;
        asm volatile("st.shared.f32 [%0], %1;" :: "r"(laddr), "f"(u));
        {
            uint32_t raddr;
            asm("mapa.shared::cluster.u32 %0, %1, %2;" : "=r"(raddr) : "r"(laddr), "r"(prank));
            asm volatile("st.shared::cluster.f32 [%0], %1;" :: "r"(raddr), "f"(u));
            uint32_t rmbar;
            asm("mapa.shared::cluster.u32 %0, %1, %2;"
                : "=r"(rmbar) : "r"(mbarBase + (uint32_t)(nb * 8)), "r"(prank));
            asm volatile("mbarrier.arrive.release.cluster.shared::cluster.b64 _, [%0];"
                         :: "r"(rmbar) : "memory");
        }

        g_Ms[(size_t)n * DD * DD + (size_t)(r0 + rr) * DD + jgl] = u;

        __syncthreads();   // local Msm[nb] stores visible CTA-wide

        // wait for partner's 512 arrivals (acquire orders its DSMEM stores)
        asm volatile(
            "{\n\t"
            ".reg .pred P;\n\t"
            "KSW_%=:\n\t"
            "mbarrier.try_wait.parity.acquire.cluster.shared::cta.b64 P, [%0], %1, 0x989680;\n\t"
            "@!P bra KSW_%=;\n\t"
            "}"
            :: "r"(mbarBase + (uint32_t)(nb * 8)), "r"(par) : "memory");
    }

    asm volatile("barrier.cluster.arrive.aligned;" ::: "memory");
    asm volatile("barrier.cluster.wait.aligned;" ::: "memory");
}

// ---------------------------------------------------------------------------
// Kernel 3: retrieval, FFMA2 + dense b-fragment (round 13 winner).
// ---------------------------------------------------------------------------
__global__ __launch_bounds__(256, 2) void k_out(const float* __restrict__ queries,
                                                float* __restrict__ out) {
    const int n = blockIdx.z;
    const int oBase = blockIdx.x * 128;
    const int uBase = blockIdx.y * 128;

    __shared__ float Qs[2][16 * LB];
    __shared__ float Mss[2][16 * LB];

    const int tx = threadIdx.x, ty = threadIdx.y;
    const int tid = ty * 16 + tx;
    const int ul0 = tid >> 2;
    const int ul1 = ul0 + 64;
    const int dq  = (tid & 3) * 4;

    const float* __restrict__ Mbase = g_Ms + (size_t)n * DD * DD;

    const int ug0 = uBase + ul0, ug1 = uBase + ul1;
    const size_t qoff0 = ((size_t)(ug0 >> 6) * LL + n * WW + (ug0 & 63)) * DD;
    const size_t qoff1 = ((size_t)(ug1 >> 6) * LL + n * WW + (ug1 & 63)) * DD;

    uint64_t acc2[8][4];
#pragma unroll
    for (int a = 0; a < 8; a++)
#pragma unroll
        for (int b = 0; b < 4; b++) acc2[a][b] = 0ull;

    float4 q0, q1, m0, m1;
#define LOADD(D0) do {                                                         \
        q0 = *(const float4*)(queries + qoff0 + (D0) + dq);                    \
        q1 = *(const float4*)(queries + qoff1 + (D0) + dq);                    \
        m0 = *(const float4*)(Mbase + (size_t)(oBase + ul0) * DD + (D0) + dq); \
        m1 = *(const float4*)(Mbase + (size_t)(oBase + ul1) * DD + (D0) + dq); \
    } while (0)

#define STORED(BUF) do {                                                       \
        Qs[BUF][(dq + 0) * LB + ul0] = q0.x; Qs[BUF][(dq + 1) * LB + ul0] = q0.y; \
        Qs[BUF][(dq + 2) * LB + ul0] = q0.z; Qs[BUF][(dq + 3) * LB + ul0] = q0.w; \
        Qs[BUF][(dq + 0) * LB + ul1] = q1.x; Qs[BUF][(dq + 1) * LB + ul1] = q1.y; \
        Qs[BUF][(dq + 2) * LB + ul1] = q1.z; Qs[BUF][(dq + 3) * LB + ul1] = q1.w; \
        Mss[BUF][(dq + 0) * LB + ul0] = m0.x; Mss[BUF][(dq + 1) * LB + ul0] = m0.y; \
        Mss[BUF][(dq + 2) * LB + ul0] = m0.z; Mss[BUF][(dq + 3) * LB + ul0] = m0.w; \
        Mss[BUF][(dq + 0) * LB + ul1] = m1.x; Mss[BUF][(dq + 1) * LB + ul1] = m1.y; \
        Mss[BUF][(dq + 2) * LB + ul1] = m1.z; Mss[BUF][(dq + 3) * LB + ul1] = m1.w; \
    } while (0)

    LOADD(0);
    STORED(0);
    LOADD(16);
    __syncthreads();

    for (int c = 0; c < 16; c++) {
        const int cur = c & 1;
        if (c < 15) STORED(cur ^ 1);
        if (c < 14) LOADD((c + 2) * 16);

#pragma unroll
        for (int kk = 0; kk < 16; kk++) {
            float4 la0 = *(const float4*)&Qs[cur][kk * LB + ty * 8];
            float4 la1 = *(const float4*)&Qs[cur][kk * LB + ty * 8 + 4];
            ulonglong2 lbp0 = *(const ulonglong2*)&Mss[cur][kk * LB + tx * 4];
            ulonglong2 lbp1 = *(const ulonglong2*)&Mss[cur][kk * LB + 64 + tx * 4];
            float laf[8] = {la0.x, la0.y, la0.z, la0.w, la1.x, la1.y, la1.z, la1.w};
#pragma unroll
            for (int a = 0; a < 8; a++) {
                const uint64_t ap = pk2(laf[a]);
                fma2(acc2[a][0], ap, lbp0.x);
                fma2(acc2[a][1], ap, lbp0.y);
                fma2(acc2[a][2], ap, lbp1.x);
                fma2(acc2[a][3], ap, lbp1.y);
            }
        }
        __syncthreads();
    }
#undef LOADD
#undef STORED

#pragma unroll
    for (int a = 0; a < 8; a++) {
        const int u = uBase + ty * 8 + a;
        const size_t orow = ((size_t)(u >> 6) * LL + n * WW + (u & 63)) * DD;
        float f[8];
        float2 p;
        p = up2(acc2[a][0]); f[0] = p.x; f[1] = p.y;
        p = up2(acc2[a][1]); f[2] = p.x; f[3] = p.y;
        p = up2(acc2[a][2]); f[4] = p.x; f[5] = p.y;
        p = up2(acc2[a][3]); f[6] = p.x; f[7] = p.y;
        *(float4*)(out + orow + oBase + tx * 4)      = *(float4*)&f[0];
        *(float4*)(out + orow + oBase + 64 + tx * 4) = *(float4*)&f[4];
    }
}

// ---------------------------------------------------------------------------
extern "C" void kernel_launch(void* const* d_in, const int* in_sizes, int n_in,
                              void* d_out, int out_size) {
    const float* keys    = (const float*)d_in[0];
    const float* values  = (const float*)d_in[1];
    const float* queries = (const float*)d_in[2];
    const float* gammas  = (const float*)d_in[3];
    const float* alpha   = (const float*)d_in[4];
    float* out = (float*)d_out;

    (void)in_sizes; (void)n_in; (void)out_size;

    dim3 blk(16, 16);
    k_sums<<<dim3(2, 2, NW * 2), blk>>>(keys, values, gammas, alpha);
    k_scan<<<128, 512>>>();
    k_out<<<dim3(2, 4, NW), blk>>>(queries, out);
}